// round 16
// baseline (speedup 1.0000x reference)
#include <cuda_runtime.h>
#include <cuda_bf16.h>
#include <stdint.h>

#define N_NODES 100000
#define N_EDGES 1200000
#define D 64

// Persistent scratch: agg = scatter_sum(relu(x[src] + e)); zeroed by memset.
__device__ __align__(16) float g_agg[(size_t)N_NODES * D];

// ---------------------------------------------------------------------------
// Kernel 1: per-edge message + scatter reduce (L2-transit bound, unchanged).
// ---------------------------------------------------------------------------
__global__ void edge_kernel(const float* __restrict__ x,
                            const int* __restrict__ ei,
                            const float* __restrict__ ea) {
    int t = blockIdx.x * blockDim.x + threadIdx.x;
    const int total = N_EDGES * 16;
    if (t >= total) return;
    int e = t >> 4;
    int c = t & 15;

    int src = __ldg(ei + e);
    int dst = __ldg(ei + N_EDGES + e);

    float4 xv = __ldg(reinterpret_cast<const float4*>(x) + (size_t)src * (D / 4) + c);
    float4 ev = __ldcs(reinterpret_cast<const float4*>(ea) + (size_t)e * (D / 4) + c);

    float4 m;
    m.x = fmaxf(xv.x + ev.x, 0.0f);
    m.y = fmaxf(xv.y + ev.y, 0.0f);
    m.z = fmaxf(xv.z + ev.z, 0.0f);
    m.w = fmaxf(xv.w + ev.w, 0.0f);

    float* p = g_agg + (size_t)dst * D + c * 4;
    asm volatile("red.global.add.v4.f32 [%0], {%1, %2, %3, %4};"
                 :: "l"(p), "f"(m.x), "f"(m.y), "f"(m.z), "f"(m.w)
                 : "memory");
}

// ---------------------------------------------------------------------------
// Kernel 2: bf16 split-precision mma.sync MLP with ldmatrix fragment loads.
//   out = relu((x+agg) @ W1 + b1) @ W2 + b2
// 2-term bf16 split: D = Ahi*Bhi + Ahi*Blo + Alo*Bhi (fp32 accum).
// Block = 128 thr / 4 warps, tile = 64 nodes. Warp w: rows w*16..+15.
// A row-major [n][k], B col-major [j][k], stride AS=72 bf16 (36 words)
// -> ldmatrix 8-row addresses hit banks 4j..4j+3: conflict-free.
// Per layer per warp: 8 A-ldmatrix.x4 + 32 B-ldmatrix.x4 + 96 mma.
// ---------------------------------------------------------------------------
#define AS 72
#define SM_AHI 0
#define SM_ALO (64 * AS)
#define SM_BHI (2 * 64 * AS)
#define SM_BLO (3 * 64 * AS)

__device__ __forceinline__ void mma_bf16(float d[4],
                                         uint32_t a0, uint32_t a1,
                                         uint32_t a2, uint32_t a3,
                                         uint32_t b0, uint32_t b1) {
    asm volatile(
        "mma.sync.aligned.m16n8k16.row.col.f32.bf16.bf16.f32 "
        "{%0,%1,%2,%3}, {%4,%5,%6,%7}, {%8,%9}, {%0,%1,%2,%3};"
        : "+f"(d[0]), "+f"(d[1]), "+f"(d[2]), "+f"(d[3])
        : "r"(a0), "r"(a1), "r"(a2), "r"(a3), "r"(b0), "r"(b1));
}

__device__ __forceinline__ void ldsm_x4(uint32_t& r0, uint32_t& r1,
                                        uint32_t& r2, uint32_t& r3,
                                        uint32_t addr) {
    asm volatile("ldmatrix.sync.aligned.m8n8.x4.shared.b16 {%0,%1,%2,%3}, [%4];"
                 : "=r"(r0), "=r"(r1), "=r"(r2), "=r"(r3) : "r"(addr));
}

__device__ __forceinline__ uint32_t pack_bf16x2(float lo, float hi) {
    __nv_bfloat162 p;
    p.x = __float2bfloat16(lo);
    p.y = __float2bfloat16(hi);
    return *reinterpret_cast<uint32_t*>(&p);
}

// Stage B[j][k] = W[k][j] as bf16 hi/lo.
__device__ __forceinline__ void stage_B(const float* __restrict__ W,
                                        __nv_bfloat16* Bhi, __nv_bfloat16* Blo) {
    for (int i = threadIdx.x; i < 64 * 16; i += 128) {
        int k = i >> 4, c = i & 15;
        float4 w = __ldg(reinterpret_cast<const float4*>(W) + i);
        float wv[4] = {w.x, w.y, w.z, w.w};
        #pragma unroll
        for (int q = 0; q < 4; ++q) {
            int j = c * 4 + q;
            __nv_bfloat16 hi = __float2bfloat16(wv[q]);
            __nv_bfloat16 lo = __float2bfloat16(wv[q] - __bfloat162float(hi));
            Bhi[j * AS + k] = hi;
            Blo[j * AS + k] = lo;
        }
    }
}

__global__ void __launch_bounds__(128)
mlp_mma_kernel(const float* __restrict__ x,
               const float* __restrict__ W1, const float* __restrict__ b1,
               const float* __restrict__ W2, const float* __restrict__ b2,
               float* __restrict__ out) {
    __shared__ __align__(16) __nv_bfloat16 sm[4 * 64 * AS];   // 36.9 KB static
    __nv_bfloat16* Ahi = sm + SM_AHI;
    __nv_bfloat16* Alo = sm + SM_ALO;
    __nv_bfloat16* Bhi = sm + SM_BHI;
    __nv_bfloat16* Blo = sm + SM_BLO;

    const int tid = threadIdx.x;
    const int node0 = blockIdx.x * 64;

    // Stage A = h = x + agg (EPS=0) as bf16 hi/lo, row-major [n][k].
    {
        const float4* ag = reinterpret_cast<const float4*>(g_agg);
        const float4* xg = reinterpret_cast<const float4*>(x);
        #pragma unroll
        for (int i = tid; i < 64 * 16; i += 128) {
            int n = i >> 4, c = i & 15;
            int node = node0 + n;
            if (node >= N_NODES) node = N_NODES - 1;
            size_t gi = (size_t)node * 16 + c;
            float4 a = ag[gi];
            float4 v = __ldg(xg + gi);
            float hv[4] = {a.x + v.x, a.y + v.y, a.z + v.z, a.w + v.w};
            float hi[4], lo[4];
            #pragma unroll
            for (int q = 0; q < 4; ++q) {
                hi[q] = __bfloat162float(__float2bfloat16(hv[q]));
                lo[q] = hv[q] - hi[q];
            }
            uint2 phi = make_uint2(pack_bf16x2(hi[0], hi[1]), pack_bf16x2(hi[2], hi[3]));
            uint2 plo = make_uint2(pack_bf16x2(lo[0], lo[1]), pack_bf16x2(lo[2], lo[3]));
            *reinterpret_cast<uint2*>(Ahi + n * AS + c * 4) = phi;
            *reinterpret_cast<uint2*>(Alo + n * AS + c * 4) = plo;
        }
    }
    stage_B(W1, Bhi, Blo);
    __syncthreads();

    const int lane = tid & 31;
    const int g = lane >> 2;         // 0..7
    const int t = lane & 3;          // 0..3
    const int m0 = (tid >> 5) * 16;  // warp's M-tile base row

    // ldmatrix lane-address components.
    const int a_row  = m0 + (lane & 15);          // A: lanes 0-15 rows, 16-31 k+8
    const int a_koff = (lane & 16) ? 8 : 0;
    const int b_rowl = lane & 7;                  // B: row j within nt-tile
    const int b_koff = 8 * (lane >> 3);           // k-offsets 0/8/16/24

    const uint32_t sAhi = (uint32_t)__cvta_generic_to_shared(Ahi);
    const uint32_t sAlo = (uint32_t)__cvta_generic_to_shared(Alo);
    const uint32_t sBhi = (uint32_t)__cvta_generic_to_shared(Bhi);
    const uint32_t sBlo = (uint32_t)__cvta_generic_to_shared(Blo);

    float acc[8][4];
    #pragma unroll
    for (int nt = 0; nt < 8; ++nt)
        #pragma unroll
        for (int r = 0; r < 4; ++r) acc[nt][r] = 0.0f;

    // ================= Layer 1 =================
    #pragma unroll
    for (int kc2 = 0; kc2 < 2; ++kc2) {
        const int kc = kc2 * 32;
        uint32_t aA = (uint32_t)((a_row * AS + kc + a_koff) * 2);
        uint32_t ah0, ah1, ah2, ah3, ah4, ah5, ah6, ah7;
        uint32_t al0, al1, al2, al3, al4, al5, al6, al7;
        ldsm_x4(ah0, ah1, ah2, ah3, sAhi + aA);
        ldsm_x4(ah4, ah5, ah6, ah7, sAhi + aA + 32);   // +16 elems
        ldsm_x4(al0, al1, al2, al3, sAlo + aA);
        ldsm_x4(al4, al5, al6, al7, sAlo + aA + 32);
        #pragma unroll
        for (int nt = 0; nt < 8; ++nt) {
            uint32_t bB = (uint32_t)(((nt * 8 + b_rowl) * AS + kc + b_koff) * 2);
            uint32_t bh0, bh1, bh2, bh3, bl0, bl1, bl2, bl3;
            ldsm_x4(bh0, bh1, bh2, bh3, sBhi + bB);
            ldsm_x4(bl0, bl1, bl2, bl3, sBlo + bB);
            mma_bf16(acc[nt], ah0, ah1, ah2, ah3, bh0, bh1);
            mma_bf16(acc[nt], ah4, ah5, ah6, ah7, bh2, bh3);
            mma_bf16(acc[nt], ah0, ah1, ah2, ah3, bl0, bl1);
            mma_bf16(acc[nt], ah4, ah5, ah6, ah7, bl2, bl3);
            mma_bf16(acc[nt], al0, al1, al2, al3, bh0, bh1);
            mma_bf16(acc[nt], al4, al5, al6, al7, bh2, bh3);
        }
    }
    __syncthreads();   // all warps done reading A (h) and B (W1)

    // Epilogue 1: t = relu(acc + b1) -> back into Ahi/Alo.
    #pragma unroll
    for (int nt = 0; nt < 8; ++nt) {
        int col = nt * 8 + 2 * t;
        float2 bb = __ldg(reinterpret_cast<const float2*>(b1 + col));
        float v0 = fmaxf(acc[nt][0] + bb.x, 0.0f);
        float v1 = fmaxf(acc[nt][1] + bb.y, 0.0f);
        float v2 = fmaxf(acc[nt][2] + bb.x, 0.0f);
        float v3 = fmaxf(acc[nt][3] + bb.y, 0.0f);
        float h0 = __bfloat162float(__float2bfloat16(v0));
        float h1 = __bfloat162float(__float2bfloat16(v1));
        float h2 = __bfloat162float(__float2bfloat16(v2));
        float h3 = __bfloat162float(__float2bfloat16(v3));
        *reinterpret_cast<uint32_t*>(Ahi + (m0 + g) * AS + col)     = pack_bf16x2(h0, h1);
        *reinterpret_cast<uint32_t*>(Ahi + (m0 + g + 8) * AS + col) = pack_bf16x2(h2, h3);
        *reinterpret_cast<uint32_t*>(Alo + (m0 + g) * AS + col)     = pack_bf16x2(v0 - h0, v1 - h1);
        *reinterpret_cast<uint32_t*>(Alo + (m0 + g + 8) * AS + col) = pack_bf16x2(v2 - h2, v3 - h3);
        acc[nt][0] = 0.0f; acc[nt][1] = 0.0f; acc[nt][2] = 0.0f; acc[nt][3] = 0.0f;
    }
    stage_B(W2, Bhi, Blo);
    __syncthreads();

    // ================= Layer 2 =================
    #pragma unroll
    for (int kc2 = 0; kc2 < 2; ++kc2) {
        const int kc = kc2 * 32;
        uint32_t aA = (uint32_t)((a_row * AS + kc + a_koff) * 2);
        uint32_t ah0, ah1, ah2, ah3, ah4, ah5, ah6, ah7;
        uint32_t al0, al1, al2, al3, al4, al5, al6, al7;
        ldsm_x4(ah0, ah1, ah2, ah3, sAhi + aA);
        ldsm_x4(ah4, ah5, ah6, ah7, sAhi + aA + 32);
        ldsm_x4(al0, al1, al2, al3, sAlo + aA);
        ldsm_x4(al4, al5, al6, al7, sAlo + aA + 32);
        #pragma unroll
        for (int nt = 0; nt < 8; ++nt) {
            uint32_t bB = (uint32_t)(((nt * 8 + b_rowl) * AS + kc + b_koff) * 2);
            uint32_t bh0, bh1, bh2, bh3, bl0, bl1, bl2, bl3;
            ldsm_x4(bh0, bh1, bh2, bh3, sBhi + bB);
            ldsm_x4(bl0, bl1, bl2, bl3, sBlo + bB);
            mma_bf16(acc[nt], ah0, ah1, ah2, ah3, bh0, bh1);
            mma_bf16(acc[nt], ah4, ah5, ah6, ah7, bh2, bh3);
            mma_bf16(acc[nt], ah0, ah1, ah2, ah3, bl0, bl1);
            mma_bf16(acc[nt], ah4, ah5, ah6, ah7, bl2, bl3);
            mma_bf16(acc[nt], al0, al1, al2, al3, bh0, bh1);
            mma_bf16(acc[nt], al4, al5, al6, al7, bh2, bh3);
        }
    }

    // Final epilogue: out = acc + b2 (guarded float2 stores).
    int nodeA = node0 + m0 + g;
    int nodeB = nodeA + 8;
    #pragma unroll
    for (int nt = 0; nt < 8; ++nt) {
        int col = nt * 8 + 2 * t;
        float2 bb = __ldg(reinterpret_cast<const float2*>(b2 + col));
        if (nodeA < N_NODES) {
            float2 v = make_float2(acc[nt][0] + bb.x, acc[nt][1] + bb.y);
            *reinterpret_cast<float2*>(out + (size_t)nodeA * D + col) = v;
        }
        if (nodeB < N_NODES) {
            float2 v = make_float2(acc[nt][2] + bb.x, acc[nt][3] + bb.y);
            *reinterpret_cast<float2*>(out + (size_t)nodeB * D + col) = v;
        }
    }
}

// ---------------------------------------------------------------------------
// Launch.
// ---------------------------------------------------------------------------
extern "C" void kernel_launch(void* const* d_in, const int* in_sizes, int n_in,
                              void* d_out, int out_size) {
    const float* x   = (const float*)d_in[0];
    const int*   ei  = (const int*)d_in[1];
    const float* ea  = (const float*)d_in[2];
    const float* W1  = (const float*)d_in[3];
    const float* b1  = (const float*)d_in[4];
    const float* W2  = (const float*)d_in[5];
    const float* b2  = (const float*)d_in[6];
    float*       out = (float*)d_out;

    // agg <- 0 (graph-capturable)
    void* aggp = nullptr;
    cudaGetSymbolAddress(&aggp, g_agg);
    cudaMemsetAsync(aggp, 0, sizeof(float) * (size_t)N_NODES * D);

    {   // scatter-sum messages
        int total = N_EDGES * 16;
        edge_kernel<<<(total + 255) / 256, 256>>>(x, ei, ea);
    }
    {   // tensor-core (mma.sync + ldmatrix) MLP: 1563 tiles of 64 nodes
        int grid = (N_NODES + 63) / 64;
        mlp_mma_kernel<<<grid, 128>>>(x, W1, b1, W2, b2, out);
    }
}

// round 17
// speedup vs baseline: 1.0225x; 1.0225x over previous
#include <cuda_runtime.h>
#include <cuda_bf16.h>
#include <stdint.h>

#define N_NODES 100000
#define N_EDGES 1200000
#define D 64

// ---------------------------------------------------------------------------
// Persistent scratch (static __device__ — no allocation).
// ---------------------------------------------------------------------------
__device__ __align__(16) float g_h[(size_t)N_NODES * D];  // h = x + agg
__device__ int  g_cnt[N_NODES];          // per-dst histogram
__device__ int  g_ptr[N_NODES + 1];      // CSR row starts (exclusive scan)
__device__ int  g_cur[N_NODES];          // scatter cursors
__device__ int2 g_edge[N_EDGES];         // binned (eid, src) pairs
__device__ int  g_bsum[256];             // block sums for 2-level scan

#define SCAN_B 512
#define SCAN_G ((N_NODES + SCAN_B - 1) / SCAN_B)   // 196

// ---------------------------------------------------------------------------
// f32x2 packed-FMA helpers (FFMA2 — PTX-only).
// ---------------------------------------------------------------------------
__device__ __forceinline__ unsigned long long pk2(float lo, float hi) {
    unsigned long long r;
    asm("mov.b64 %0, {%1, %2};" : "=l"(r) : "f"(lo), "f"(hi));
    return r;
}
__device__ __forceinline__ unsigned long long ffma2(unsigned long long a,
                                                    unsigned long long b,
                                                    unsigned long long c) {
    unsigned long long d;
    asm("fma.rn.f32x2 %0, %1, %2, %3;" : "=l"(d) : "l"(a), "l"(b), "l"(c));
    return d;
}
__device__ __forceinline__ void upk2(unsigned long long v, float& lo, float& hi) {
    asm("mov.b64 {%0, %1}, %2;" : "=f"(lo), "=f"(hi) : "l"(v));
}

// ---------------------------------------------------------------------------
// Phase 1: histogram of destination nodes.
// ---------------------------------------------------------------------------
__global__ void hist_kernel(const int* __restrict__ ei) {
    int e = blockIdx.x * blockDim.x + threadIdx.x;
    if (e < N_EDGES) atomicAdd(&g_cnt[__ldg(ei + N_EDGES + e)], 1);
}

// ---------------------------------------------------------------------------
// Phase 2: two-level exclusive scan of g_cnt -> g_ptr (+ block sums).
// ---------------------------------------------------------------------------
__global__ void scan1_kernel() {
    __shared__ int sh[SCAN_B];
    int t = threadIdx.x, b = blockIdx.x;
    int i = b * SCAN_B + t;
    int v = (i < N_NODES) ? g_cnt[i] : 0;
    sh[t] = v;
    __syncthreads();
    #pragma unroll
    for (int off = 1; off < SCAN_B; off <<= 1) {
        int add = (t >= off) ? sh[t - off] : 0;
        __syncthreads();
        sh[t] += add;
        __syncthreads();
    }
    if (i < N_NODES) g_ptr[i] = sh[t] - v;       // local exclusive
    if (t == SCAN_B - 1) g_bsum[b] = sh[t];       // block total
}

__global__ void scan2_kernel() {   // 1 block, 256 threads; SCAN_G <= 256
    __shared__ int sh[256];
    int t = threadIdx.x;
    int v = (t < SCAN_G) ? g_bsum[t] : 0;
    sh[t] = v;
    __syncthreads();
    #pragma unroll
    for (int off = 1; off < 256; off <<= 1) {
        int add = (t >= off) ? sh[t - off] : 0;
        __syncthreads();
        sh[t] += add;
        __syncthreads();
    }
    if (t < SCAN_G) g_bsum[t] = sh[t] - v;        // exclusive block offsets
}

__global__ void scan3_kernel() {
    int i = blockIdx.x * blockDim.x + threadIdx.x;
    if (i < N_NODES) {
        int p = g_ptr[i] + g_bsum[i / SCAN_B];
        g_ptr[i] = p;
        g_cur[i] = p;
    }
    if (i == 0) g_ptr[N_NODES] = N_EDGES;
}

// ---------------------------------------------------------------------------
// Phase 3: scatter (eid, src) into dst bins.
// ---------------------------------------------------------------------------
__global__ void scatter_kernel(const int* __restrict__ ei) {
    int e = blockIdx.x * blockDim.x + threadIdx.x;
    if (e >= N_EDGES) return;
    int src = __ldg(ei + e);
    int dst = __ldg(ei + N_EDGES + e);
    int p = atomicAdd(&g_cur[dst], 1);
    g_edge[p] = make_int2(e, src);
}

// ---------------------------------------------------------------------------
// Phase 4: gather-reduce. 16 threads per node (one float4 lane each):
//   h[node] = x[node] + sum_{edges in bin} relu(x[src] + ea[eid])
// No atomics; ea row reads coalesced within the 16-lane group.
// ---------------------------------------------------------------------------
__global__ void gather_kernel(const float* __restrict__ x,
                              const float* __restrict__ ea) {
    int tid = blockIdx.x * blockDim.x + threadIdx.x;
    int node = tid >> 4;
    int c = tid & 15;
    if (node >= N_NODES) return;

    int start = __ldg(g_ptr + node);
    int end   = __ldg(g_ptr + node + 1);

    float4 acc = make_float4(0.f, 0.f, 0.f, 0.f);
    const float4* xg = reinterpret_cast<const float4*>(x);
    const float4* eg = reinterpret_cast<const float4*>(ea);

    for (int i = start; i < end; ++i) {
        int2 es = __ldg(&g_edge[i]);          // (eid, src) — broadcast in group
        float4 ev = __ldcs(eg + (size_t)es.x * 16 + c);
        float4 xv = __ldg(xg + (size_t)es.y * 16 + c);
        acc.x += fmaxf(xv.x + ev.x, 0.0f);
        acc.y += fmaxf(xv.y + ev.y, 0.0f);
        acc.z += fmaxf(xv.z + ev.z, 0.0f);
        acc.w += fmaxf(xv.w + ev.w, 0.0f);
    }

    float4 xs = __ldg(xg + (size_t)node * 16 + c);
    acc.x += xs.x; acc.y += xs.y; acc.z += xs.z; acc.w += xs.w;
    reinterpret_cast<float4*>(g_h)[(size_t)node * 16 + c] = acc;
}

// ---------------------------------------------------------------------------
// MLP (best-measured R11 variant, reading g_h).
//   out = relu(h @ W1 + b1) @ W2 + b2
// Block = 128 thr, TILE_N = 128 nodes; thread = 8 nodes x 8 cols; per k:
// 4 LDS.128 feed 32 FFMA2. hsT transposed, 132-float pad. 50 KB dyn smem.
// ---------------------------------------------------------------------------
#define TILE_N 128
#define HT_PAD 132
#define SMEM_HST_FLOATS (D * HT_PAD)
#define SMEM_TOTAL_BYTES ((SMEM_HST_FLOATS + D * D) * 4)   // 50176

extern __shared__ float smem_dyn[];

__device__ __forceinline__ void gemm_pass(const float* hsT, const float* Ws,
                                          int ng, int cg,
                                          unsigned long long acc[8][4]) {
    #pragma unroll 8
    for (int k = 0; k < D; ++k) {
        const float* hrow = hsT + k * HT_PAD + ng * 8;
        float4 hv0 = *reinterpret_cast<const float4*>(hrow);
        float4 hv1 = *reinterpret_cast<const float4*>(hrow + 4);
        ulonglong2 wp0 = *reinterpret_cast<const ulonglong2*>(Ws + k * D + cg * 4);
        ulonglong2 wp1 = *reinterpret_cast<const ulonglong2*>(Ws + k * D + 32 + cg * 4);

        unsigned long long h[8];
        h[0] = pk2(hv0.x, hv0.x); h[1] = pk2(hv0.y, hv0.y);
        h[2] = pk2(hv0.z, hv0.z); h[3] = pk2(hv0.w, hv0.w);
        h[4] = pk2(hv1.x, hv1.x); h[5] = pk2(hv1.y, hv1.y);
        h[6] = pk2(hv1.z, hv1.z); h[7] = pk2(hv1.w, hv1.w);

        #pragma unroll
        for (int n = 0; n < 8; ++n) {
            acc[n][0] = ffma2(h[n], wp0.x, acc[n][0]);
            acc[n][1] = ffma2(h[n], wp0.y, acc[n][1]);
            acc[n][2] = ffma2(h[n], wp1.x, acc[n][2]);
            acc[n][3] = ffma2(h[n], wp1.y, acc[n][3]);
        }
    }
}

__global__ void __launch_bounds__(128)
mlp_kernel(const float* __restrict__ W1, const float* __restrict__ b1,
           const float* __restrict__ W2, const float* __restrict__ b2,
           float* __restrict__ out) {
    float* hsT = smem_dyn;
    float* Ws  = smem_dyn + SMEM_HST_FLOATS;

    const int tid = threadIdx.x;
    const int node0 = blockIdx.x * TILE_N;
    const int cg = tid & 7;
    const int ng = tid >> 3;

    {
        const float4* wg = reinterpret_cast<const float4*>(W1);
        float4* ws = reinterpret_cast<float4*>(Ws);
        #pragma unroll
        for (int i = tid; i < D * D / 4; i += 128) ws[i] = wg[i];
    }
    {
        const float4* hg = reinterpret_cast<const float4*>(g_h);
        #pragma unroll
        for (int i = tid; i < TILE_N * (D / 4); i += 128) {
            int n = i >> 4;
            int c = i & 15;
            int node = node0 + n;
            if (node >= N_NODES) node = N_NODES - 1;
            float4 a = __ldcs(hg + (size_t)node * (D / 4) + c);
            hsT[(c * 4 + 0) * HT_PAD + n] = a.x;
            hsT[(c * 4 + 1) * HT_PAD + n] = a.y;
            hsT[(c * 4 + 2) * HT_PAD + n] = a.z;
            hsT[(c * 4 + 3) * HT_PAD + n] = a.w;
        }
    }
    __syncthreads();

    float4 b1a = __ldg(reinterpret_cast<const float4*>(b1) + cg);
    float4 b1b = __ldg(reinterpret_cast<const float4*>(b1) + 8 + cg);
    float4 b2a = __ldg(reinterpret_cast<const float4*>(b2) + cg);
    float4 b2b = __ldg(reinterpret_cast<const float4*>(b2) + 8 + cg);

    unsigned long long acc[8][4];

    {
        unsigned long long i0 = pk2(b1a.x, b1a.y), i1 = pk2(b1a.z, b1a.w);
        unsigned long long i2 = pk2(b1b.x, b1b.y), i3 = pk2(b1b.z, b1b.w);
        #pragma unroll
        for (int n = 0; n < 8; ++n) {
            acc[n][0] = i0; acc[n][1] = i1; acc[n][2] = i2; acc[n][3] = i3;
        }
    }
    gemm_pass(hsT, Ws, ng, cg, acc);

    float o[8][8];
    #pragma unroll
    for (int n = 0; n < 8; ++n) {
        upk2(acc[n][0], o[n][0], o[n][1]);
        upk2(acc[n][1], o[n][2], o[n][3]);
        upk2(acc[n][2], o[n][4], o[n][5]);
        upk2(acc[n][3], o[n][6], o[n][7]);
        #pragma unroll
        for (int j = 0; j < 8; ++j) o[n][j] = fmaxf(o[n][j], 0.0f);
    }

    __syncthreads();

    #pragma unroll
    for (int j = 0; j < 8; ++j) {
        int col = (j < 4) ? (cg * 4 + j) : (32 + cg * 4 + (j - 4));
        float* r = hsT + col * HT_PAD + ng * 8;
        *reinterpret_cast<float4*>(r)     = make_float4(o[0][j], o[1][j], o[2][j], o[3][j]);
        *reinterpret_cast<float4*>(r + 4) = make_float4(o[4][j], o[5][j], o[6][j], o[7][j]);
    }
    {
        const float4* wg = reinterpret_cast<const float4*>(W2);
        float4* ws = reinterpret_cast<float4*>(Ws);
        #pragma unroll
        for (int i = tid; i < D * D / 4; i += 128) ws[i] = wg[i];
    }
    __syncthreads();

    {
        unsigned long long i0 = pk2(b2a.x, b2a.y), i1 = pk2(b2a.z, b2a.w);
        unsigned long long i2 = pk2(b2b.x, b2b.y), i3 = pk2(b2b.z, b2b.w);
        #pragma unroll
        for (int n = 0; n < 8; ++n) {
            acc[n][0] = i0; acc[n][1] = i1; acc[n][2] = i2; acc[n][3] = i3;
        }
    }
    gemm_pass(hsT, Ws, ng, cg, acc);

    float4* ob = reinterpret_cast<float4*>(out);
    #pragma unroll
    for (int n = 0; n < 8; ++n) {
        int node = node0 + ng * 8 + n;
        if (node < N_NODES) {
            float a, b, c, d2;
            upk2(acc[n][0], a, b); upk2(acc[n][1], c, d2);
            ob[(size_t)node * (D / 4) + cg] = make_float4(a, b, c, d2);
            upk2(acc[n][2], a, b); upk2(acc[n][3], c, d2);
            ob[(size_t)node * (D / 4) + 8 + cg] = make_float4(a, b, c, d2);
        }
    }
}

// ---------------------------------------------------------------------------
// Launch. Inputs: x f32[100000*64], edge_index i32[2*1200000],
// edge_attr f32[1200000*64], W1, b1, W2, b2. Output f32[100000*64].
// ---------------------------------------------------------------------------
extern "C" void kernel_launch(void* const* d_in, const int* in_sizes, int n_in,
                              void* d_out, int out_size) {
    const float* x   = (const float*)d_in[0];
    const int*   ei  = (const int*)d_in[1];
    const float* ea  = (const float*)d_in[2];
    const float* W1  = (const float*)d_in[3];
    const float* b1  = (const float*)d_in[4];
    const float* W2  = (const float*)d_in[5];
    const float* b2  = (const float*)d_in[6];
    float*       out = (float*)d_out;

    // counters <- 0 (tiny, graph-capturable)
    void* cntp = nullptr;
    cudaGetSymbolAddress(&cntp, g_cnt);
    cudaMemsetAsync(cntp, 0, sizeof(int) * N_NODES);

    // CSR build
    hist_kernel<<<(N_EDGES + 255) / 256, 256>>>(ei);
    scan1_kernel<<<SCAN_G, SCAN_B>>>();
    scan2_kernel<<<1, 256>>>();
    scan3_kernel<<<(N_NODES + 255) / 256, 256>>>();
    scatter_kernel<<<(N_EDGES + 255) / 256, 256>>>(ei);

    // gather-reduce: h = x + scatter_sum(relu(x[src]+ea))
    gather_kernel<<<(N_NODES * 16 + 255) / 256, 256>>>(x, ea);

    // MLP
    {
        static bool attr_set = false;
        if (!attr_set) {
            cudaFuncSetAttribute(mlp_kernel,
                                 cudaFuncAttributeMaxDynamicSharedMemorySize,
                                 SMEM_TOTAL_BYTES);
            attr_set = true;
        }
        int grid = (N_NODES + TILE_N - 1) / TILE_N;
        mlp_kernel<<<grid, 128, SMEM_TOTAL_BYTES>>>(W1, b1, W2, b2, out);
    }
}